// round 4
// baseline (speedup 1.0000x reference)
#include <cuda_runtime.h>
#include <math.h>

#define DIM 16777216
#define NVEC (DIM / 4)          // 4,194,304 float4 elements
#define THREADS 256
#define BLOCKS (NVEC / THREADS) // 16384

// Zero-initialized at module load; the last finishing block resets them at the
// end of every launch, so each launch sees zeros (graph-replay deterministic).
__device__ float        g_sum_dev2;
__device__ float        g_sum_css2;
__device__ unsigned int g_ticket;

__device__ __forceinline__ float4 ldcs4(const float4* p) {
    float4 v;
    asm volatile("ld.global.cs.v4.f32 {%0,%1,%2,%3}, [%4];"
                 : "=f"(v.x), "=f"(v.y), "=f"(v.z), "=f"(v.w) : "l"(p));
    return v;
}
__device__ __forceinline__ void stcs4(float4* p, float4 v) {
    asm volatile("st.global.cs.v4.f32 [%0], {%1,%2,%3,%4};"
                 :: "l"(p), "f"(v.x), "f"(v.y), "f"(v.z), "f"(v.w));
}

__global__ void __launch_bounds__(THREADS) ni_fused_kernel(
    const float* __restrict__ css_in,   // (4, DIM)
    const float* __restrict__ narr,     // (DIM,)
    const float* __restrict__ tonic,    // (DIM,)
    const float* __restrict__ fast_p,   // scalar
    const float* __restrict__ slow_p,   // scalar
    float* __restrict__ out)            // [0:DIM)=new_narrative, [DIM:2DIM)=velocity, [2DIM:2DIM+3)=scalars
{
    const int i = blockIdx.x * blockDim.x + threadIdx.x;  // float4 index

    const float4* a0 = reinterpret_cast<const float4*>(css_in);
    const float4* a1 = a0 + NVEC;
    const float4* a2 = a1 + NVEC;
    const float4* a3 = a2 + NVEC;
    const float4* n4 = reinterpret_cast<const float4*>(narr);
    const float4* t4 = reinterpret_cast<const float4*>(tonic);
    float4* out_nn  = reinterpret_cast<float4*>(out);
    float4* out_vel = out_nn + NVEC;

    float4 v0 = ldcs4(a0 + i);
    float4 v1 = ldcs4(a1 + i);
    float4 v2 = ldcs4(a2 + i);
    float4 v3 = ldcs4(a3 + i);
    float4 n  = ldcs4(n4 + i);
    float4 t  = ldcs4(t4 + i);

    float dev2 = 0.0f;
    float c2   = 0.0f;
    float4 nn, vel;

    {
        float css = (v0.x + v1.x + v2.x + v3.x) * 0.25f;
        float d   = css - n.x;
        dev2 = fmaf(d, d, dev2);  c2 = fmaf(css, css, c2);
        nn.x  = fmaf(n.x, 0.99f, fmaf(css, 0.01f, t.x));
        vel.x = nn.x - n.x;
    }
    {
        float css = (v0.y + v1.y + v2.y + v3.y) * 0.25f;
        float d   = css - n.y;
        dev2 = fmaf(d, d, dev2);  c2 = fmaf(css, css, c2);
        nn.y  = fmaf(n.y, 0.99f, fmaf(css, 0.01f, t.y));
        vel.y = nn.y - n.y;
    }
    {
        float css = (v0.z + v1.z + v2.z + v3.z) * 0.25f;
        float d   = css - n.z;
        dev2 = fmaf(d, d, dev2);  c2 = fmaf(css, css, c2);
        nn.z  = fmaf(n.z, 0.99f, fmaf(css, 0.01f, t.z));
        vel.z = nn.z - n.z;
    }
    {
        float css = (v0.w + v1.w + v2.w + v3.w) * 0.25f;
        float d   = css - n.w;
        dev2 = fmaf(d, d, dev2);  c2 = fmaf(css, css, c2);
        nn.w  = fmaf(n.w, 0.99f, fmaf(css, 0.01f, t.w));
        vel.w = nn.w - n.w;
    }

    stcs4(out_nn + i,  nn);
    stcs4(out_vel + i, vel);

    // Warp-level reduce both sums
    #pragma unroll
    for (int off = 16; off > 0; off >>= 1) {
        dev2 += __shfl_down_sync(0xFFFFFFFFu, dev2, off);
        c2   += __shfl_down_sync(0xFFFFFFFFu, c2,   off);
    }

    __shared__ float s_dev[THREADS / 32];
    __shared__ float s_css[THREADS / 32];
    const int lane = threadIdx.x & 31;
    const int wid  = threadIdx.x >> 5;
    if (lane == 0) { s_dev[wid] = dev2; s_css[wid] = c2; }
    __syncthreads();

    if (wid == 0) {
        dev2 = (lane < THREADS / 32) ? s_dev[lane] : 0.0f;
        c2   = (lane < THREADS / 32) ? s_css[lane] : 0.0f;
        #pragma unroll
        for (int off = 4; off > 0; off >>= 1) {
            dev2 += __shfl_down_sync(0xFFFFFFFFu, dev2, off);
            c2   += __shfl_down_sync(0xFFFFFFFFu, c2,   off);
        }
        if (lane == 0) {
            atomicAdd(&g_sum_dev2, dev2);
            atomicAdd(&g_sum_css2, c2);
            __threadfence();  // make sums visible before ticket increment
            unsigned int t = atomicAdd(&g_ticket, 1u);
            if (t == (unsigned int)(BLOCKS - 1)) {
                // Last block: compute scalar epilogue, then reset state.
                const float sum_dev2 = atomicAdd(&g_sum_dev2, 0.0f);
                const float sum_css2 = atomicAdd(&g_sum_css2, 0.0f);
                const float dev_norm = sqrtf(sum_dev2);
                const float css_norm = sqrtf(sum_css2);
                const float fast = fast_p[0];
                const float slow = slow_p[0];

                const float consistency_loss = 0.1f * dev_norm;

                const float input_gate = fminf(1.0f, css_norm);
                const float delta_fast = 0.01f / (1.0f + fast * 5.0f) * input_gate;
                const float fast_new   = fminf(fast * 0.9995f + delta_fast, 0.7f);

                const float schema_fit  = fminf(fmaxf(1.0f - dev_norm, 0.0f), 1.0f);
                const float schema_mult = 1.0f + 15.0f * schema_fit * schema_fit;
                const float delta_slow  = 0.001f / (1.0f + slow * 5.0f) * schema_mult;
                const float slow_new    = fminf(slow + delta_slow, 1.0f);

                const float identity_strength = fminf(fast_new + slow_new, 1.0f);

                out[2 * DIM + 0] = consistency_loss;
                out[2 * DIM + 1] = identity_strength;
                out[2 * DIM + 2] = dev_norm;

                // Reset for the next (graph-replayed) launch.
                g_sum_dev2 = 0.0f;
                g_sum_css2 = 0.0f;
                __threadfence();
                g_ticket = 0u;
            }
        }
    }
}

extern "C" void kernel_launch(void* const* d_in, const int* in_sizes, int n_in,
                              void* d_out, int out_size)
{
    const float* css   = (const float*)d_in[0];  // (4, DIM)
    const float* narr  = (const float*)d_in[1];  // (DIM,)
    const float* tonic = (const float*)d_in[2];  // (DIM,)
    const float* fast  = (const float*)d_in[3];  // scalar
    const float* slow  = (const float*)d_in[4];  // scalar
    float* out = (float*)d_out;

    ni_fused_kernel<<<BLOCKS, THREADS>>>(css, narr, tonic, fast, slow, out);
}

// round 5
// speedup vs baseline: 1.0004x; 1.0004x over previous
#include <cuda_runtime.h>
#include <math.h>

#define DIM 16777216
#define NVEC (DIM / 4)          // 4,194,304 float4 elements
#define THREADS 256
#define BLOCKS (NVEC / THREADS) // 16384

// Zero-initialized at module load; the last finishing block resets them at the
// end of every launch, so each launch sees zeros (graph-replay deterministic).
__device__ float        g_sum_dev2;
__device__ float        g_sum_css2;
__device__ unsigned int g_ticket;

__device__ __forceinline__ float4 ldcs4(const float4* p) {
    float4 v;
    asm volatile("ld.global.cs.v4.f32 {%0,%1,%2,%3}, [%4];"
                 : "=f"(v.x), "=f"(v.y), "=f"(v.z), "=f"(v.w) : "l"(p));
    return v;
}
__device__ __forceinline__ void stcs4(float4* p, float4 v) {
    asm volatile("st.global.cs.v4.f32 [%0], {%1,%2,%3,%4};"
                 :: "l"(p), "f"(v.x), "f"(v.y), "f"(v.z), "f"(v.w));
}

__global__ void __launch_bounds__(THREADS) ni_fused_kernel(
    const float* __restrict__ css_in,   // (4, DIM)
    const float* __restrict__ narr,     // (DIM,)
    const float* __restrict__ tonic,    // (DIM,)
    const float* __restrict__ fast_p,   // scalar
    const float* __restrict__ slow_p,   // scalar
    float* __restrict__ out)            // [0:DIM)=new_narrative, [DIM:2DIM)=velocity, [2DIM:2DIM+3)=scalars
{
    const int i = blockIdx.x * blockDim.x + threadIdx.x;  // float4 index

    const float4* a0 = reinterpret_cast<const float4*>(css_in);
    const float4* a1 = a0 + NVEC;
    const float4* a2 = a1 + NVEC;
    const float4* a3 = a2 + NVEC;
    const float4* n4 = reinterpret_cast<const float4*>(narr);
    const float4* t4 = reinterpret_cast<const float4*>(tonic);
    float4* out_nn  = reinterpret_cast<float4*>(out);
    float4* out_vel = out_nn + NVEC;

    float4 v0 = ldcs4(a0 + i);
    float4 v1 = ldcs4(a1 + i);
    float4 v2 = ldcs4(a2 + i);
    float4 v3 = ldcs4(a3 + i);
    float4 n  = ldcs4(n4 + i);
    float4 t  = ldcs4(t4 + i);

    float dev2 = 0.0f;
    float c2   = 0.0f;
    float4 nn, vel;

    {
        float css = (v0.x + v1.x + v2.x + v3.x) * 0.25f;
        float d   = css - n.x;
        dev2 = fmaf(d, d, dev2);  c2 = fmaf(css, css, c2);
        nn.x  = fmaf(n.x, 0.99f, fmaf(css, 0.01f, t.x));
        vel.x = nn.x - n.x;
    }
    {
        float css = (v0.y + v1.y + v2.y + v3.y) * 0.25f;
        float d   = css - n.y;
        dev2 = fmaf(d, d, dev2);  c2 = fmaf(css, css, c2);
        nn.y  = fmaf(n.y, 0.99f, fmaf(css, 0.01f, t.y));
        vel.y = nn.y - n.y;
    }
    {
        float css = (v0.z + v1.z + v2.z + v3.z) * 0.25f;
        float d   = css - n.z;
        dev2 = fmaf(d, d, dev2);  c2 = fmaf(css, css, c2);
        nn.z  = fmaf(n.z, 0.99f, fmaf(css, 0.01f, t.z));
        vel.z = nn.z - n.z;
    }
    {
        float css = (v0.w + v1.w + v2.w + v3.w) * 0.25f;
        float d   = css - n.w;
        dev2 = fmaf(d, d, dev2);  c2 = fmaf(css, css, c2);
        nn.w  = fmaf(n.w, 0.99f, fmaf(css, 0.01f, t.w));
        vel.w = nn.w - n.w;
    }

    stcs4(out_nn + i,  nn);
    stcs4(out_vel + i, vel);

    // Warp-level reduce both sums
    #pragma unroll
    for (int off = 16; off > 0; off >>= 1) {
        dev2 += __shfl_down_sync(0xFFFFFFFFu, dev2, off);
        c2   += __shfl_down_sync(0xFFFFFFFFu, c2,   off);
    }

    __shared__ float s_dev[THREADS / 32];
    __shared__ float s_css[THREADS / 32];
    const int lane = threadIdx.x & 31;
    const int wid  = threadIdx.x >> 5;
    if (lane == 0) { s_dev[wid] = dev2; s_css[wid] = c2; }
    __syncthreads();

    if (wid == 0) {
        dev2 = (lane < THREADS / 32) ? s_dev[lane] : 0.0f;
        c2   = (lane < THREADS / 32) ? s_css[lane] : 0.0f;
        #pragma unroll
        for (int off = 4; off > 0; off >>= 1) {
            dev2 += __shfl_down_sync(0xFFFFFFFFu, dev2, off);
            c2   += __shfl_down_sync(0xFFFFFFFFu, c2,   off);
        }
        if (lane == 0) {
            atomicAdd(&g_sum_dev2, dev2);
            atomicAdd(&g_sum_css2, c2);
            __threadfence();  // make sums visible before ticket increment
            unsigned int t = atomicAdd(&g_ticket, 1u);
            if (t == (unsigned int)(BLOCKS - 1)) {
                // Last block: compute scalar epilogue, then reset state.
                const float sum_dev2 = atomicAdd(&g_sum_dev2, 0.0f);
                const float sum_css2 = atomicAdd(&g_sum_css2, 0.0f);
                const float dev_norm = sqrtf(sum_dev2);
                const float css_norm = sqrtf(sum_css2);
                const float fast = fast_p[0];
                const float slow = slow_p[0];

                const float consistency_loss = 0.1f * dev_norm;

                const float input_gate = fminf(1.0f, css_norm);
                const float delta_fast = 0.01f / (1.0f + fast * 5.0f) * input_gate;
                const float fast_new   = fminf(fast * 0.9995f + delta_fast, 0.7f);

                const float schema_fit  = fminf(fmaxf(1.0f - dev_norm, 0.0f), 1.0f);
                const float schema_mult = 1.0f + 15.0f * schema_fit * schema_fit;
                const float delta_slow  = 0.001f / (1.0f + slow * 5.0f) * schema_mult;
                const float slow_new    = fminf(slow + delta_slow, 1.0f);

                const float identity_strength = fminf(fast_new + slow_new, 1.0f);

                out[2 * DIM + 0] = consistency_loss;
                out[2 * DIM + 1] = identity_strength;
                out[2 * DIM + 2] = dev_norm;

                // Reset for the next (graph-replayed) launch.
                g_sum_dev2 = 0.0f;
                g_sum_css2 = 0.0f;
                __threadfence();
                g_ticket = 0u;
            }
        }
    }
}

extern "C" void kernel_launch(void* const* d_in, const int* in_sizes, int n_in,
                              void* d_out, int out_size)
{
    const float* css   = (const float*)d_in[0];  // (4, DIM)
    const float* narr  = (const float*)d_in[1];  // (DIM,)
    const float* tonic = (const float*)d_in[2];  // (DIM,)
    const float* fast  = (const float*)d_in[3];  // scalar
    const float* slow  = (const float*)d_in[4];  // scalar
    float* out = (float*)d_out;

    ni_fused_kernel<<<BLOCKS, THREADS>>>(css, narr, tonic, fast, slow, out);
}